// round 17
// baseline (speedup 1.0000x reference)
#include <cuda_runtime.h>

// Problem constants
#define NN   50000
#define EE   600000
#define HH   128
#define LL   4
#define GG   64
#define EMBD 64
#define CC   10
#define LH   (LL*HH)        // 512
#define ZIN  (LH+EMBD)      // 576
#define H1D  256            // 2*H
#define BN_EPS 1e-5f

// ---------------- device scratch (static, allocation-guard safe) -------------
__device__ __align__(16) float g_h2a[NN*HH];   // layer output ping
__device__ __align__(16) float g_h2b[NN*HH];   // layer output pong
__device__ __align__(16) float g_bnsum[2*HH];  // per-col sum / sumsq
__device__ __align__(16) float g_bna[LH];      // per-layer BN affine scale a
__device__ __align__(16) float g_bnd[LH];      // per-layer BN affine shift d
__device__ __align__(16) float g_pool[GG*LH];  // pooled h2 sums per graph
__device__ __align__(16) float g_cnt[GG];      // nodes per graph
// CSR (rebuilt every call — deterministic)
__device__ int g_rowptr[NN+1];
__device__ int g_cursor[NN];
__device__ int g_col[EE];

// ---------------- vectorized global reduction --------------------------------
__device__ __forceinline__ void red_add_v4(float* p, float4 v) {
    asm volatile("red.global.add.v4.f32 [%0], {%1,%2,%3,%4};"
                 :: "l"(p), "f"(v.x), "f"(v.y), "f"(v.z), "f"(v.w)
                 : "memory");
}

// ---------------- zero / CSR build kernels -----------------------------------
__global__ void k_zero_pool() {
    int i = blockIdx.x * blockDim.x + threadIdx.x;
    if (i < GG*LH) g_pool[i] = 0.f;
}
__global__ void k_zero_bn() {
    if (threadIdx.x < 2*HH) g_bnsum[threadIdx.x] = 0.f;
}
__global__ void k_zero_rp() {
    int i = blockIdx.x * blockDim.x + threadIdx.x;
    if (i < NN+1) g_rowptr[i] = 0;
}
__global__ void k_deg(const int* __restrict__ ei) {
    int e = blockIdx.x * blockDim.x + threadIdx.x;
    if (e < EE) atomicAdd(&g_rowptr[ei[EE + e] + 1], 1);
}
__global__ __launch_bounds__(1024)
void k_scan() {
    __shared__ int carry;
    __shared__ int warpsum[32];
    int tid = threadIdx.x, lane = tid & 31, w = tid >> 5;
    if (tid == 0) carry = 0;
    __syncthreads();
    for (int base = 0; base < NN+1; base += 1024) {
        int i = base + tid;
        int v = (i <= NN) ? g_rowptr[i] : 0;
        int s = v;
#pragma unroll
        for (int o = 1; o < 32; o <<= 1) {
            int t = __shfl_up_sync(0xFFFFFFFFu, s, o);
            if (lane >= o) s += t;
        }
        if (lane == 31) warpsum[w] = s;
        __syncthreads();
        if (w == 0) {
            int ws = warpsum[lane];
#pragma unroll
            for (int o = 1; o < 32; o <<= 1) {
                int t = __shfl_up_sync(0xFFFFFFFFu, ws, o);
                if (lane >= o) ws += t;
            }
            warpsum[lane] = ws;
        }
        __syncthreads();
        int incl = s + (w ? warpsum[w-1] : 0) + carry;
        if (i <= NN) g_rowptr[i] = incl;
        if (i <  NN) g_cursor[i] = incl;
        int total = warpsum[31] + carry;
        __syncthreads();
        if (tid == 0) carry = total;
        __syncthreads();
    }
}
__global__ void k_fill(const int* __restrict__ ei) {
    int e = blockIdx.x * blockDim.x + threadIdx.x;
    if (e >= EE) return;
    int d = ei[EE + e];
    int pos = atomicAdd(&g_cursor[d], 1);
    g_col[pos] = ei[e];
}
// nodes per graph via binary search on sorted batch
__global__ void k_cnt(const int* __restrict__ batch) {
    int g = threadIdx.x;
    if (g >= GG) return;
    int lo = 0, hi = NN;
    while (lo < hi) { int m = (lo+hi) >> 1; if (batch[m] < g) lo = m+1; else hi = m; }
    int first = lo;
    lo = 0; hi = NN;
    while (lo < hi) { int m = (lo+hi) >> 1; if (batch[m] < g+1) lo = m+1; else hi = m; }
    g_cnt[g] = (float)(lo - first);
}

// ---------------- BN affine constants for layer l (+ reset stats) ------------
__global__ void k_bnaff(const float* __restrict__ gamma,
                        const float* __restrict__ beta, int l) {
    int c = threadIdx.x;
    if (c >= HH) return;
    const float inv = 1.0f / (float)NN;
    float mean = g_bnsum[c] * inv;
    float var  = g_bnsum[HH+c] * inv - mean*mean;
    float a = gamma[l*HH + c] * rsqrtf(var + BN_EPS);
    g_bna[l*HH + c] = a;
    g_bnd[l*HH + c] = beta[l*HH + c] - mean * a;
    g_bnsum[c] = 0.f;          // reset for next layer
    g_bnsum[HH+c] = 0.f;
}

// ---------------- mega kernel: gather + double SGEMM + stats + pooling -------
// Phase 0: CSR gather (+BN affine of prev layer) -> Af[128][132] smem tile
//          src is the PREVIOUS layer's output buffer (ping-pong — never the
//          same buffer this kernel writes, eliminating the cross-block race).
// Stage 1: h1 = relu(Af @ W1 + b1)  (h1 overwrites Af)
// Stage 2: C  = relu(h1 @ W2 + b2); epilogue: BN stats + pooled per-graph reds
// BM=128, BN=128, BK=16, 256 threads, 8x8 per thread.
__global__ __launch_bounds__(256)
void k_gemm_all(const float* __restrict__ src,
                const float* __restrict__ eps,
                const float* __restrict__ W1, const float* __restrict__ b1,
                const float* __restrict__ W2, const float* __restrict__ b2,
                float* __restrict__ C,
                const int* __restrict__ batch, int l) {
    extern __shared__ float smem[];
    float (*Af)[132] = (float(*)[132])smem;                  // 128x132 (A / h1)
    float (*As)[128] = (float(*)[128])(smem + 128*132);      // 16x128 transposed chunk
    float (*Bs)[128] = (float(*)[128])(smem + 128*132 + 16*128);
    float* ssum = smem + 128*132 + 2*16*128;                 // 128
    float* ssq  = ssum + 128;                                // 128

    int tid = threadIdx.x;
    int lane = tid & 31;
    int wrp  = tid >> 5;
    int blockRow = blockIdx.x * 128;

    if (tid < 128) { ssum[tid] = 0.f; ssq[tid] = 0.f; }

    // -------- phase 0: gather 16 rows per warp --------
    {
        const float4* x4 = (const float4*)src;
        float s = 1.0f + eps[l];
        for (int rr = 0; rr < 16; rr++) {
            int local = wrp*16 + rr;
            int row   = blockRow + local;
            float4 acc = make_float4(0.f,0.f,0.f,0.f);
            if (row < NN) {
                acc = x4[(size_t)row*32 + lane];
                acc.x *= s; acc.y *= s; acc.z *= s; acc.w *= s;
                int e0  = g_rowptr[row];
                int end = g_rowptr[row+1];
                int e = e0;
                for (; e + 1 < end; e += 2) {
                    int s0 = g_col[e], s1 = g_col[e+1];
                    float4 v0 = x4[(size_t)s0*32 + lane];
                    float4 v1 = x4[(size_t)s1*32 + lane];
                    acc.x += v0.x + v1.x;
                    acc.y += v0.y + v1.y;
                    acc.z += v0.z + v1.z;
                    acc.w += v0.w + v1.w;
                }
                if (e < end) {
                    int s0 = g_col[e];
                    float4 v0 = x4[(size_t)s0*32 + lane];
                    acc.x += v0.x; acc.y += v0.y; acc.z += v0.z; acc.w += v0.w;
                }
                if (l > 0) {
                    float4 a = *(const float4*)(g_bna + (l-1)*HH + lane*4);
                    float4 d = *(const float4*)(g_bnd + (l-1)*HH + lane*4);
                    float t = s + (float)(end - e0);
                    acc.x = fmaf(a.x, acc.x, d.x*t);
                    acc.y = fmaf(a.y, acc.y, d.y*t);
                    acc.z = fmaf(a.z, acc.z, d.z*t);
                    acc.w = fmaf(a.w, acc.w, d.w*t);
                }
            }
            *(float4*)(&Af[local][lane*4]) = acc;
        }
    }
    __syncthreads();

    int aRow  = tid >> 2;          // 0..63
    int aCol4 = (tid & 3) * 4;     // 0,4,8,12
    int bRow  = tid >> 5;          // 0..7
    int bCol4 = (tid & 31) * 4;    // 0..124
    int tr = (tid >> 4) * 8;       // 0..120
    int tc = (tid & 15) * 8;       // 0..120

    float acc[8][8];
#pragma unroll
    for (int i = 0; i < 8; i++)
#pragma unroll
        for (int j = 0; j < 8; j++) acc[i][j] = 0.f;

    // -------- stage 1: acc = Af @ W1 (chunked smem->smem transpose) --------
    for (int k0 = 0; k0 < 128; k0 += 16) {
#pragma unroll
        for (int i = 0; i < 2; i++) {
            float4 v = *(const float4*)(&Af[aRow + i*64][k0 + aCol4]);
            As[aCol4+0][aRow + i*64] = v.x;
            As[aCol4+1][aRow + i*64] = v.y;
            As[aCol4+2][aRow + i*64] = v.z;
            As[aCol4+3][aRow + i*64] = v.w;
        }
#pragma unroll
        for (int i = 0; i < 2; i++) {
            float4 v = *(const float4*)(W1 + (size_t)(k0 + bRow + i*8)*128 + bCol4);
            *(float4*)(&Bs[bRow + i*8][bCol4]) = v;
        }
        __syncthreads();
#pragma unroll
        for (int k = 0; k < 16; k++) {
            float ra[8], rb[8];
            float4 a0 = *(const float4*)(&As[k][tr]);
            float4 a1 = *(const float4*)(&As[k][tr+4]);
            float4 bb0 = *(const float4*)(&Bs[k][tc]);
            float4 bb1 = *(const float4*)(&Bs[k][tc+4]);
            ra[0]=a0.x; ra[1]=a0.y; ra[2]=a0.z; ra[3]=a0.w;
            ra[4]=a1.x; ra[5]=a1.y; ra[6]=a1.z; ra[7]=a1.w;
            rb[0]=bb0.x; rb[1]=bb0.y; rb[2]=bb0.z; rb[3]=bb0.w;
            rb[4]=bb1.x; rb[5]=bb1.y; rb[6]=bb1.z; rb[7]=bb1.w;
#pragma unroll
            for (int i = 0; i < 8; i++)
#pragma unroll
                for (int j = 0; j < 8; j++)
                    acc[i][j] += ra[i]*rb[j];
        }
        __syncthreads();
    }

    // epilogue 1: bias+relu, h1 overwrites Af
    {
        float rb1[8];
#pragma unroll
        for (int j = 0; j < 8; j++) rb1[j] = b1[tc+j];
#pragma unroll
        for (int i = 0; i < 8; i++) {
            float4 v0, v1;
            v0.x = fmaxf(acc[i][0] + rb1[0], 0.f);
            v0.y = fmaxf(acc[i][1] + rb1[1], 0.f);
            v0.z = fmaxf(acc[i][2] + rb1[2], 0.f);
            v0.w = fmaxf(acc[i][3] + rb1[3], 0.f);
            v1.x = fmaxf(acc[i][4] + rb1[4], 0.f);
            v1.y = fmaxf(acc[i][5] + rb1[5], 0.f);
            v1.z = fmaxf(acc[i][6] + rb1[6], 0.f);
            v1.w = fmaxf(acc[i][7] + rb1[7], 0.f);
            *(float4*)(&Af[tr+i][tc])   = v0;
            *(float4*)(&Af[tr+i][tc+4]) = v1;
        }
    }
    __syncthreads();

    // -------- stage 2: acc = Af(h1) @ W2 --------
#pragma unroll
    for (int i = 0; i < 8; i++)
#pragma unroll
        for (int j = 0; j < 8; j++) acc[i][j] = 0.f;

    for (int k0 = 0; k0 < 128; k0 += 16) {
#pragma unroll
        for (int i = 0; i < 2; i++) {
            float4 v = *(const float4*)(W2 + (size_t)(k0 + bRow + i*8)*128 + bCol4);
            *(float4*)(&Bs[bRow + i*8][bCol4]) = v;
        }
        __syncthreads();
#pragma unroll
        for (int k = 0; k < 16; k++) {
            float ra[8], rb[8];
            float4 bb0 = *(const float4*)(&Bs[k][tc]);
            float4 bb1 = *(const float4*)(&Bs[k][tc+4]);
            rb[0]=bb0.x; rb[1]=bb0.y; rb[2]=bb0.z; rb[3]=bb0.w;
            rb[4]=bb1.x; rb[5]=bb1.y; rb[6]=bb1.z; rb[7]=bb1.w;
#pragma unroll
            for (int i = 0; i < 8; i++) ra[i] = Af[tr+i][k0+k];
#pragma unroll
            for (int i = 0; i < 8; i++)
#pragma unroll
                for (int j = 0; j < 8; j++)
                    acc[i][j] += ra[i]*rb[j];
        }
        __syncthreads();
    }

    // epilogue 2: bias+relu, store C, BN stats, pooled h2 reds
    float rb2[8];
#pragma unroll
    for (int j = 0; j < 8; j++) rb2[j] = b2[tc+j];

    float csum[8], csq[8];
#pragma unroll
    for (int j = 0; j < 8; j++) { csum[j]=0.f; csq[j]=0.f; }

#pragma unroll
    for (int i = 0; i < 8; i++) {
        int r = blockRow + tr + i;
        if (r < NN) {
            float v[8];
#pragma unroll
            for (int j = 0; j < 8; j++) {
                v[j] = fmaxf(acc[i][j] + rb2[j], 0.f);
                csum[j] += v[j]; csq[j] += v[j]*v[j];
            }
            float4 q0 = make_float4(v[0],v[1],v[2],v[3]);
            float4 q1 = make_float4(v[4],v[5],v[6],v[7]);
            *(float4*)(C + (size_t)r*HH + tc)     = q0;
            *(float4*)(C + (size_t)r*HH + tc + 4) = q1;
            int b = batch[r];
            float* pp = g_pool + (size_t)b*LH + l*HH + tc;
            red_add_v4(pp,     q0);
            red_add_v4(pp + 4, q1);
        }
    }

    __syncthreads();
#pragma unroll
    for (int j = 0; j < 8; j++) {
        atomicAdd(&ssum[tc+j], csum[j]);
        atomicAdd(&ssq [tc+j], csq [j]);
    }
    __syncthreads();
    if (tid < 128) {
        atomicAdd(&g_bnsum[tid],    ssum[tid]);
        atomicAdd(&g_bnsum[HH+tid], ssq [tid]);
    }
}

// ---------------- Head: affine on pooled h2, MLP + log_softmax ---------------
__global__ __launch_bounds__(256)
void k_head(const float* __restrict__ emb,
            const float* __restrict__ l1w, const float* __restrict__ l1b,
            const float* __restrict__ l2w, const float* __restrict__ l2b,
            const float* __restrict__ l4w, const float* __restrict__ l4b,
            float* __restrict__ out) {
    __shared__ float zin[ZIN];
    __shared__ float z1[H1D];
    __shared__ float z2[HH];
    __shared__ float lg[CC];
    __shared__ float lse;

    int g = blockIdx.x, t = threadIdx.x;
    float cnt = fmaxf(g_cnt[g], 1.0f);
    for (int c = t; c < LH; c += 256)
        zin[c] = fmaf(g_bna[c], g_pool[g*LH + c] / cnt, g_bnd[c]);
    if (t < EMBD) zin[LH + t] = emb[g*EMBD + t];
    __syncthreads();

    {
        float a = l1b[t];
        for (int k = 0; k < ZIN; k++) a += zin[k] * l1w[k*H1D + t];
        z1[t] = fmaxf(a, 0.f);
    }
    __syncthreads();
    if (t < HH) {
        float a = l2b[t];
        for (int k = 0; k < H1D; k++) a += z1[k] * l2w[k*HH + t];
        z2[t] = fmaxf(a, 0.f);
    }
    __syncthreads();
    if (t < CC) {
        float a = l4b[t];
        for (int k = 0; k < HH; k++) a += z2[k] * l4w[k*CC + t];
        lg[t] = a;
    }
    __syncthreads();
    if (t == 0) {
        float m = lg[0];
        for (int i = 1; i < CC; i++) m = fmaxf(m, lg[i]);
        float s = 0.f;
        for (int i = 0; i < CC; i++) s += expf(lg[i] - m);
        lse = m + logf(s);
    }
    __syncthreads();
    if (t < CC) out[g*CC + t] = lg[t] - lse;
}

// ---------------- launch -----------------------------------------------------
extern "C" void kernel_launch(void* const* d_in, const int* in_sizes, int n_in,
                              void* d_out, int out_size) {
    const float* x     = (const float*)d_in[0];
    const int*   ei    = (const int*)  d_in[1];   // int32 (JAX x64 disabled)
    const int*   batch = (const int*)  d_in[2];   // int32
    const float* emb   = (const float*)d_in[3];
    const float* eps   = (const float*)d_in[4];
    const float* W1    = (const float*)d_in[5];
    const float* b1    = (const float*)d_in[6];
    const float* W2    = (const float*)d_in[7];
    const float* b2    = (const float*)d_in[8];
    const float* gamma = (const float*)d_in[9];
    const float* beta  = (const float*)d_in[10];
    const float* l1w   = (const float*)d_in[11];
    const float* l1b   = (const float*)d_in[12];
    const float* l2w   = (const float*)d_in[13];
    const float* l2b   = (const float*)d_in[14];
    const float* l4w   = (const float*)d_in[15];
    const float* l4b   = (const float*)d_in[16];
    float* out = (float*)d_out;

    float *h2a, *h2b;
    cudaGetSymbolAddress((void**)&h2a, g_h2a);
    cudaGetSymbolAddress((void**)&h2b, g_h2b);

    const int SMEM = (128*132 + 2*16*128 + 256) * 4;   // 84992 B -> 2 CTA/SM
    static bool attr_set = false;
    if (!attr_set) {
        cudaFuncSetAttribute(k_gemm_all,
                             cudaFuncAttributeMaxDynamicSharedMemorySize, SMEM);
        attr_set = true;
    }

    // ---- CSR build (every call; deterministic) ----
    k_zero_rp<<<(NN+1 + 255)/256, 256>>>();
    k_deg<<<(EE + 255)/256, 256>>>(ei);
    k_scan<<<1, 1024>>>();
    k_fill<<<(EE + 255)/256, 256>>>(ei);

    k_zero_pool<<<(GG*LH + 255)/256, 256>>>();
    k_cnt<<<1, GG>>>(batch);
    k_zero_bn<<<1, 256>>>();

    // ping-pong: layer l reads prev buffer, writes buf[l&1]
    float* bufs[2] = { h2a, h2b };
    for (int l = 0; l < LL; l++) {
        const float* src = (l == 0) ? x : bufs[(l-1) & 1];
        float*       dst = bufs[l & 1];
        k_gemm_all<<<(NN + 127)/128, 256, SMEM>>>(
            src, eps, W1 + l*HH*HH, b1 + l*HH, W2 + l*HH*HH, b2 + l*HH, dst,
            batch, l);
        k_bnaff<<<1, HH>>>(gamma, beta, l);
    }

    k_head<<<GG, 256>>>(emb, l1w, l1b, l2w, l2b, l4w, l4b, out);
}